// round 1
// baseline (speedup 1.0000x reference)
#include <cuda_runtime.h>
#include <math.h>

// Problem shape (fixed by setup_inputs)
#define NN 512
#define EE 64
#define OO 64
#define KK 8
#define NTHREADS 512
#define NPAD 68   // padded priors row stride (floats): 16B-aligned rows, decent bank spread

struct SmemLayout {
    float priors[NN][NPAD];   // 139264 B
    float delta[KK][NN];      //  16384 B
    float zred[16][KK][OO];   //  32768 B
    float z[KK][OO];          //   2048 B
    float v[KK][OO];          //   2048 B
    float Smat[EE][OO];       //  16384 B
};                            // total 208896 B < 227 KB dynamic smem cap

__global__ void __launch_bounds__(NTHREADS, 1)
routing_kernel(const float* __restrict__ emb,
               const float* __restrict__ S,
               const float* __restrict__ cc0,
               float* __restrict__ out)
{
    extern __shared__ __align__(16) unsigned char smraw[];
    SmemLayout& sm = *reinterpret_cast<SmemLayout*>(smraw);

    const int b    = blockIdx.x;
    const int t    = threadIdx.x;
    const int lane = t & 31;
    const int warp = t >> 5;
    const int o4   = t & 15;   // which float4 of the O=64 row
    const int ng   = t >> 4;   // n-group: handles n = ng + 32*i, i in [0,16)

    // ---- load S into smem (4096 floats) + zero delta ----
    {
        const float4* src = reinterpret_cast<const float4*>(S);
        float4* dst = reinterpret_cast<float4*>(&sm.Smat[0][0]);
        for (int i = t; i < (EE * OO) / 4; i += NTHREADS) dst[i] = src[i];
    }
    for (int i = t; i < KK * NN; i += NTHREADS) (&sm.delta[0][0])[i] = 0.0f;
    __syncthreads();

    // ---- Phase A: priors[n][o] = sum_e emb[b,n,e] * S[e,o] ----
    const float* embb = emb + (size_t)b * NN * EE;
    #pragma unroll 1
    for (int i = 0; i < 16; i++) {
        const int n = ng + 32 * i;
        const float4* erow = reinterpret_cast<const float4*>(embb + n * EE);
        float4 acc = make_float4(0.f, 0.f, 0.f, 0.f);
        #pragma unroll
        for (int e4 = 0; e4 < EE / 4; e4++) {
            float4 a  = erow[e4];  // broadcast across the 16 lanes sharing n
            float4 s0 = *reinterpret_cast<const float4*>(&sm.Smat[4*e4+0][o4*4]);
            float4 s1 = *reinterpret_cast<const float4*>(&sm.Smat[4*e4+1][o4*4]);
            float4 s2 = *reinterpret_cast<const float4*>(&sm.Smat[4*e4+2][o4*4]);
            float4 s3 = *reinterpret_cast<const float4*>(&sm.Smat[4*e4+3][o4*4]);
            acc.x += a.x*s0.x + a.y*s1.x + a.z*s2.x + a.w*s3.x;
            acc.y += a.x*s0.y + a.y*s1.y + a.z*s2.y + a.w*s3.y;
            acc.z += a.x*s0.z + a.y*s1.z + a.z*s2.z + a.w*s3.z;
            acc.w += a.x*s0.w + a.y*s1.w + a.z*s2.w + a.w*s3.w;
        }
        *reinterpret_cast<float4*>(&sm.priors[n][o4 * 4]) = acc;
    }
    __syncthreads();

    // ---- Routing iterations (all in-CTA; only cc0 streams from HBM) ----
    const float* ccb = cc0 + (size_t)b * KK * NN * OO;

    #pragma unroll 1
    for (int it = 0; it < 3; it++) {
        float4 zp[KK];
        #pragma unroll
        for (int k = 0; k < KK; k++) zp[k] = make_float4(0.f, 0.f, 0.f, 0.f);

        // prefetch cc0 block for i=0
        float4 cb[KK];
        #pragma unroll
        for (int k = 0; k < KK; k++)
            cb[k] = *reinterpret_cast<const float4*>(ccb + ((size_t)k * NN + ng) * OO + o4 * 4);

        #pragma unroll 2
        for (int i = 0; i < 16; i++) {
            const int n = ng + 32 * i;
            float4 c[KK];
            #pragma unroll
            for (int k = 0; k < KK; k++) c[k] = cb[k];
            if (i < 15) {
                const int n2 = n + 32;
                #pragma unroll
                for (int k = 0; k < KK; k++)
                    cb[k] = *reinterpret_cast<const float4*>(ccb + ((size_t)k * NN + n2) * OO + o4 * 4);
            }

            // per-n delta and its max over k (k-constant shift => identical softmax)
            float d[KK];
            float dmax = -1e30f;
            #pragma unroll
            for (int k = 0; k < KK; k++) { d[k] = sm.delta[k][n]; dmax = fmaxf(dmax, d[k]); }

            float4 p = *reinterpret_cast<const float4*>(&sm.priors[n][o4 * 4]);

            float sx = 0.f, sy = 0.f, sz = 0.f, sw = 0.f;
            #pragma unroll
            for (int k = 0; k < KK; k++) {
                const float dk = d[k] - dmax;
                c[k].x = __expf(c[k].x + dk); sx += c[k].x;
                c[k].y = __expf(c[k].y + dk); sy += c[k].y;
                c[k].z = __expf(c[k].z + dk); sz += c[k].z;
                c[k].w = __expf(c[k].w + dk); sw += c[k].w;
            }
            const float gx = __fdividef(p.x, sx);
            const float gy = __fdividef(p.y, sy);
            const float gz = __fdividef(p.z, sz);
            const float gw = __fdividef(p.w, sw);
            #pragma unroll
            for (int k = 0; k < KK; k++) {
                zp[k].x += c[k].x * gx;
                zp[k].y += c[k].y * gy;
                zp[k].z += c[k].z * gz;
                zp[k].w += c[k].w * gw;
            }
        }

        // ---- reduce z partials: lane^16 shares o4 ----
        #pragma unroll
        for (int k = 0; k < KK; k++) {
            zp[k].x += __shfl_xor_sync(0xffffffffu, zp[k].x, 16);
            zp[k].y += __shfl_xor_sync(0xffffffffu, zp[k].y, 16);
            zp[k].z += __shfl_xor_sync(0xffffffffu, zp[k].z, 16);
            zp[k].w += __shfl_xor_sync(0xffffffffu, zp[k].w, 16);
        }
        if (lane < 16) {
            #pragma unroll
            for (int k = 0; k < KK; k++)
                *reinterpret_cast<float4*>(&sm.zred[warp][k][o4 * 4]) = zp[k];
        }
        __syncthreads();
        {
            const int k = t >> 6, o = t & 63;   // 512 threads == K*O outputs
            float s = 0.f;
            #pragma unroll
            for (int w = 0; w < 16; w++) s += sm.zred[w][k][o];
            sm.z[k][o] = s;
        }
        __syncthreads();

        // ---- squash: warp w handles capsule k=w ----
        if (warp < KK) {
            const int k = warp;
            const float z0 = sm.z[k][lane];
            const float z1 = sm.z[k][lane + 32];
            float sq = z0 * z0 + z1 * z1;
            #pragma unroll
            for (int s2 = 16; s2 > 0; s2 >>= 1) sq += __shfl_xor_sync(0xffffffffu, sq, s2);
            const float f = sq / ((1.0f + sq) * sqrtf(sq + 1e-9f));
            if (it == 2) {
                float* ob = out + (size_t)b * KK * OO + (size_t)k * OO;
                ob[lane]      = f * z0;
                ob[lane + 32] = f * z1;
            } else {
                sm.v[k][lane]      = f * z0;
                sm.v[k][lane + 32] = f * z1;
            }
        }
        if (it == 2) break;
        __syncthreads();

        // ---- sim pass: delta[k][n] += <priors[n,:], v[k,:]>; thread t handles n = t ----
        {
            const int n = t;
            float sim[KK];
            #pragma unroll
            for (int k = 0; k < KK; k++) sim[k] = 0.f;
            #pragma unroll
            for (int oo = 0; oo < 16; oo++) {
                float4 pp = *reinterpret_cast<const float4*>(&sm.priors[n][oo * 4]);
                #pragma unroll
                for (int k = 0; k < KK; k++) {
                    float4 vv = *reinterpret_cast<const float4*>(&sm.v[k][oo * 4]); // broadcast
                    sim[k] += pp.x * vv.x + pp.y * vv.y + pp.z * vv.z + pp.w * vv.w;
                }
            }
            #pragma unroll
            for (int k = 0; k < KK; k++) sm.delta[k][n] += sim[k];
        }
        __syncthreads();
    }
}

extern "C" void kernel_launch(void* const* d_in, const int* in_sizes, int n_in,
                              void* d_out, int out_size)
{
    const float* emb = (const float*)d_in[0];   // (B, N, E) fp32
    const float* S   = (const float*)d_in[1];   // (E, O)   fp32
    const float* cc  = (const float*)d_in[2];   // (B, K, N, O) fp32
    float* out       = (float*)d_out;           // (B, K, O) fp32

    const int Bv = in_sizes[0] / (NN * EE);     // 256

    // Host-side attribute set: not a stream op, safe under graph capture, idempotent.
    cudaFuncSetAttribute(routing_kernel,
                         cudaFuncAttributeMaxDynamicSharedMemorySize,
                         (int)sizeof(SmemLayout));

    routing_kernel<<<Bv, NTHREADS, sizeof(SmemLayout)>>>(emb, S, cc, out);
}